// round 16
// baseline (speedup 1.0000x reference)
#include <cuda_runtime.h>
#include <cuda_bf16.h>
#include <cstdint>

// ---------------- problem constants ----------------
#define NNODES 4096
#define NBATCH 64
#define NPG    64
#define HD     128
#define HD4    32
#define NE     131072
#define EPB    2048
#define KK     52
#define NK     3328
#define NK4    (NK/4)

#define LEN_X  (NK*HD)
#define OFF_A2 (LEN_X)
#define OFF_B  (OFF_A2 + NK*NK)
#define OFF_P  (OFF_B + NK)

#define ROWU 20
#define PLUA (64*ROWU)
#define PLUB (128*ROWU)
#define BUFU (3*PLUA + 3*PLUB)
#define GSMEM (2*BUFU*4)         // 92160 bytes (k_att front region too)

#define H0W 384

// k_att smem: front 92160 B (GEMM0/1 double buffers; GEMM2 B buffers) + h1 planes
#define H1PITCH 164              // u32 per row; 164%32=4 -> conflict-free
#define H1PL    (64*H1PITCH*4)   // 41984 B per plane
#define FH1B    92160
#define ATT_SMEM (FH1B + 3*H1PL) // 218112 B

// k_fuse smem layout
#define FSC   0
#define FSL   4096
#define FXC   8192
#define FTMP  16384
#define FAGGB 98304
#define APITCH 84
#define AGPL  (64*APITCH*4)
#define FBBUF (FAGGB + 3*AGPL)
#define FUSE_SMEM (FBBUF + 30720)

// ---------------- scratch ----------------
__device__ float g_A[NBATCH*NPG*NPG];
__device__ float g_Cnt[NBATCH*NPG*NPG];
__device__ float g_S[NBATCH*NPG*NPG];
__device__ float g_xq[NNODES*HD];
__device__ float g_qt[NNODES*HD];
__device__ float g_f[2*NNODES];

__device__ __align__(16) __nv_bfloat16 g_XP  [3*NNODES*HD];
__device__ __align__(16) __nv_bfloat16 g_xcP [3*NNODES*HD];
__device__ __align__(16) __nv_bfloat16 g_WkP [3*4*128*128];
__device__ __align__(16) __nv_bfloat16 g_W1P [3*4*256*H0W];
__device__ __align__(16) __nv_bfloat16 g_W2P [3*4*128*256];
__device__ __align__(16) __nv_bfloat16 g_LWP [3*2*128*128];
__device__ __align__(16) __nv_bfloat16 g_h0P [3*2*NNODES*H0W];

__device__ __forceinline__ float lrelu(float v){ return v > 0.f ? v : 0.01f*v; }

__device__ __forceinline__ void split3(float a, unsigned short& h0, unsigned short& h1, unsigned short& h2){
    __nv_bfloat16 b0 = __float2bfloat16(a); float r1 = a - __bfloat162float(b0);
    __nv_bfloat16 b1 = __float2bfloat16(r1); float r2 = r1 - __bfloat162float(b1);
    __nv_bfloat16 b2 = __float2bfloat16(r2);
    h0 = __bfloat16_as_ushort(b0);
    h1 = __bfloat16_as_ushort(b1);
    h2 = __bfloat16_as_ushort(b2);
}
__device__ __forceinline__ void split2pack(float a, float b, uint32_t& p0, uint32_t& p1, uint32_t& p2){
    unsigned short a0,a1,a2,b0,b1,b2;
    split3(a, a0, a1, a2);
    split3(b, b0, b1, b2);
    p0 = (uint32_t)a0 | ((uint32_t)b0 << 16);
    p1 = (uint32_t)a1 | ((uint32_t)b1 << 16);
    p2 = (uint32_t)a2 | ((uint32_t)b2 << 16);
}

__device__ __forceinline__ void mma16816(float* d, const uint32_t* a, const uint32_t* b){
    asm volatile(
        "mma.sync.aligned.m16n8k16.row.col.f32.bf16.bf16.f32 "
        "{%0,%1,%2,%3}, {%4,%5,%6,%7}, {%8,%9}, {%0,%1,%2,%3};"
        : "+f"(d[0]), "+f"(d[1]), "+f"(d[2]), "+f"(d[3])
        : "r"(a[0]), "r"(a[1]), "r"(a[2]), "r"(a[3]), "r"(b[0]), "r"(b[1]));
}

__device__ __forceinline__ void ldm4(uint32_t* r, uint32_t addr){
    asm volatile("ldmatrix.sync.aligned.m8n8.x4.shared.b16 {%0,%1,%2,%3}, [%4];"
        : "=r"(r[0]), "=r"(r[1]), "=r"(r[2]), "=r"(r[3]) : "r"(addr));
}

__device__ __forceinline__ void cpasync16(uint32_t dst, const void* src){
    asm volatile("cp.async.ca.shared.global [%0], [%1], 16;" :: "r"(dst), "l"(src) : "memory");
}
#define CP_COMMIT() asm volatile("cp.async.commit_group;" ::: "memory")
#define CP_WAIT0()  asm volatile("cp.async.wait_group 0;" ::: "memory")

// ---------------- cp.async fill (A 64 rows, B 128 rows, 32 k, 128 threads) ----------------
#define ISSUECOPY(AP, aZ, aP, BP, bZ, bP, KTOT, K0, BUFB)                                  \
    _Pragma("unroll")                                                                      \
    for (int p=0; p<3; p++){                                                               \
        _Pragma("unroll")                                                                  \
        for (int it=0; it<2; it++){                                                        \
            int e = t + it*128;                                                            \
            int ar = e >> 2, aq = e & 3;                                                   \
            const __nv_bfloat16* as = (AP) + (size_t)p*(aP) + (size_t)z*(aZ)               \
                + (size_t)(rowBase+ar)*(KTOT) + (K0) + aq*8;                               \
            cpasync16(sbb + (BUFB) + p*(PLUA*4) + ar*80 + aq*16, as);                      \
        }                                                                                  \
        _Pragma("unroll")                                                                  \
        for (int it=0; it<4; it++){                                                        \
            int e = t + it*128;                                                            \
            int br = e >> 2, bq = e & 3;                                                   \
            const __nv_bfloat16* bs = (BP) + (size_t)p*(bP) + (size_t)z*(bZ)               \
                + (size_t)(colBase+br)*(KTOT) + (K0) + bq*8;                               \
            cpasync16(sbb + (BUFB) + (3*PLUA + p*PLUB)*4 + br*80 + bq*16, bs);             \
        }                                                                                  \
    }                                                                                      \
    CP_COMMIT();

#define MMACHUNK(BUFB)                                                                     \
    _Pragma("unroll")                                                                      \
    for (int s=0; s<2; s++){                                                               \
        uint32_t bf[3][4][2];                                                              \
        _Pragma("unroll")                                                                  \
        for (int p=0; p<3; p++){                                                           \
            _Pragma("unroll")                                                              \
            for (int pi=0; pi<2; pi++){                                                    \
                uint32_t r4[4];                                                            \
                ldm4(r4, sbb + (BUFB) + (3*PLUA + p*PLUB)*4 + bRowBase + pi*(16*ROWU*4) + s*32); \
                bf[p][2*pi][0]=r4[0];   bf[p][2*pi][1]=r4[1];                              \
                bf[p][2*pi+1][0]=r4[2]; bf[p][2*pi+1][1]=r4[3];                            \
            }                                                                              \
        }                                                                                  \
        _Pragma("unroll")                                                                  \
        for (int apl=0; apl<3; apl++){                                                     \
            uint32_t af[4][4];                                                             \
            _Pragma("unroll")                                                              \
            for (int mi=0; mi<4; mi++)                                                     \
                ldm4(af[mi], sbb + (BUFB) + apl*(PLUA*4) + aRowBase + mi*(16*ROWU*4) + s*32);\
            int nb = (apl==0)?3:((apl==1)?2:1);                                            \
            _Pragma("unroll")                                                              \
            for (int bpl=0; bpl<3; bpl++){                                                 \
                if (bpl >= nb) break;                                                      \
                _Pragma("unroll")                                                          \
                for (int mi=0; mi<4; mi++)                                                 \
                    _Pragma("unroll")                                                      \
                    for (int ni=0; ni<4; ni++)                                             \
                        mma16816(acc[mi*4+ni], af[mi], bf[bpl][ni]);                       \
            }                                                                              \
        }                                                                                  \
    }

#define GEMM_MAINLOOP(AP, aZ, aP, BP, bZ, bP, KTOT)                                        \
    int chunks = (KTOT) >> 5;                                                              \
    int quad = lane >> 3, qi = lane & 7;                                                   \
    uint32_t aRowBase = (uint32_t)((quad&1)*8 + qi)*(ROWU*4) + (quad>>1)*16;               \
    uint32_t bRowBase = (uint32_t)(warpN + (quad>>1)*8 + qi)*(ROWU*4) + (quad&1)*16;       \
    ISSUECOPY(AP, aZ, aP, BP, bZ, bP, KTOT, 0, 0)                                          \
    CP_WAIT0();                                                                            \
    __syncthreads();                                                                       \
    for (int c = 0; c < chunks; c++){                                                      \
        uint32_t curB = (uint32_t)(c & 1)*(BUFU*4);                                        \
        uint32_t nxtB = (uint32_t)((c + 1) & 1)*(BUFU*4);                                  \
        if (c + 1 < chunks){ ISSUECOPY(AP, aZ, aP, BP, bZ, bP, KTOT, (c+1) << 5, nxtB) }   \
        MMACHUNK(curB)                                                                     \
        if (c + 1 < chunks){ CP_WAIT0(); }                                                 \
        __syncthreads();                                                                   \
    }

// ---------------- fused attention: Wk GEMM -> h0 -> W1 GEMM -> h1(smem) -> W2 GEMM -> w3 -> softmax ----
// grid (1, 64, 2), 128 threads. blockIdx.y = row block (batch), blockIdx.z = z.
__global__ void __launch_bounds__(128) k_att(
    int base,
    const __nv_bfloat16* __restrict__ kvP,
    const float* __restrict__ q0, const float* __restrict__ q1,
    const float* __restrict__ W3)
{
    extern __shared__ uint32_t smu[];
    __shared__ float sw3[128];
    __shared__ float slog[4][64];
    __shared__ float sl[64];
    __shared__ float sred[64];
    int t = threadIdx.x, wid = t >> 5, lane = t & 31;
    int z = blockIdx.z;
    int rowBase = blockIdx.y * 64;
    int warpN = wid * 32;
    uint32_t sbb;
    asm("{ .reg .u64 tt; cvta.to.shared.u64 tt, %1; cvt.u32.u64 %0, tt; }" : "=r"(sbb) : "l"(smu));

    if (t < 128) sw3[t] = W3[(size_t)(base+z)*128 + t];

    float acc[16][4];

    // ---- GEMM0: a = kv @ Wk -> h0P [a, q, a*q] ----
#pragma unroll
    for (int i=0;i<16;i++){ acc[i][0]=0.f; acc[i][1]=0.f; acc[i][2]=0.f; acc[i][3]=0.f; }
    {
        int colBase = 0;
        GEMM_MAINLOOP(kvP, 0LL, (long long)NNODES*HD,
                      g_WkP + (size_t)base*16384, 16384LL, 4LL*16384, 128)
    }
    {
        const float* q = z ? q1 : q0;
#pragma unroll
        for (int mi=0; mi<4; mi++){
#pragma unroll
            for (int ni=0; ni<4; ni++){
                float* d = acc[mi*4+ni];
                int r0 = rowBase + mi*16 + (lane>>2);
                int c0 = warpN + ni*8 + (lane&3)*2;
#pragma unroll
                for (int qi2=0; qi2<2; qi2++){
                    int row = r0 + qi2*8;
                    float av = d[qi2*2], bv = d[qi2*2+1];
                    float qa = q[(size_t)row*128 + c0];
                    float qb = q[(size_t)row*128 + c0 + 1];
                    float sa[3] = {av, qa, av*qa};
                    float sb[3] = {bv, qb, bv*qb};
#pragma unroll
                    for (int sec=0; sec<3; sec++){
                        uint32_t p0,p1,p2;
                        split2pack(sa[sec], sb[sec], p0, p1, p2);
                        size_t off = (size_t)z*(NNODES*H0W) + (size_t)row*H0W + sec*128 + c0;
                        *(uint32_t*)(g_h0P + off)                      = p0;
                        *(uint32_t*)(g_h0P + 2LL*NNODES*H0W + off)     = p1;
                        *(uint32_t*)(g_h0P + 4LL*NNODES*H0W + off)     = p2;
                    }
                }
            }
        }
    }
    __syncthreads();

    // ---- GEMM1: h1 = lrelu(h0 @ W1), two N-halves -> smem h1 planes ----
    for (int xh = 0; xh < 2; xh++){
#pragma unroll
        for (int i=0;i<16;i++){ acc[i][0]=0.f; acc[i][1]=0.f; acc[i][2]=0.f; acc[i][3]=0.f; }
        {
            int colBase = xh*128;
            GEMM_MAINLOOP(g_h0P, (long long)NNODES*H0W, 2LL*NNODES*H0W,
                          g_W1P + (size_t)base*256*H0W, 256LL*H0W, 4LL*256*H0W, H0W)
        }
#pragma unroll
        for (int mi=0; mi<4; mi++){
#pragma unroll
            for (int ni=0; ni<4; ni++){
                float* d = acc[mi*4+ni];
                int r0 = mi*16 + (lane>>2);
                int c0 = xh*128 + warpN + ni*8 + (lane&3)*2;
#pragma unroll
                for (int qi2=0; qi2<2; qi2++){
                    int row = r0 + qi2*8;
                    float da = lrelu(d[qi2*2]), db = lrelu(d[qi2*2+1]);
                    uint32_t p0,p1,p2;
                    split2pack(da, db, p0, p1, p2);
                    uint32_t bidx = (uint32_t)row*H1PITCH + (uint32_t)(c0>>5)*20 + ((c0&31)>>1);
                    uint32_t* h1u = smu + FH1B/4;
                    h1u[bidx]              = p0;
                    h1u[H1PL/4 + bidx]     = p1;
                    h1u[2*(H1PL/4) + bidx] = p2;
                }
            }
        }
        __syncthreads();
    }

    // ---- GEMM2: h2 = lrelu(h1 @ W2), K=256 from smem planes; W2 double-buffered ----
#pragma unroll
    for (int i=0;i<16;i++){ acc[i][0]=0.f; acc[i][1]=0.f; acc[i][2]=0.f; acc[i][3]=0.f; }
    {
        int quad = lane >> 3, qi = lane & 7;
        uint32_t aR2 = sbb + (uint32_t)FH1B + (uint32_t)((quad&1)*8 + qi)*(H1PITCH*4) + (quad>>1)*16;
        uint32_t bR2 = (uint32_t)(warpN + (quad>>1)*8 + qi)*80 + (quad&1)*16;
        const __nv_bfloat16* W2b = g_W2P + (size_t)(base+z)*32768;
        // prefill chunk 0
        for (int u = t; u < 1536; u += 128){
            int p = u / 512, rem = u - p*512;
            int n = rem >> 2, q = rem & 3;
            cpasync16(sbb + p*10240 + n*80 + q*16, W2b + (size_t)p*(4*32768) + (size_t)n*256 + q*8);
        }
        CP_COMMIT(); CP_WAIT0();
        __syncthreads();
        for (int c = 0; c < 8; c++){
            uint32_t curB = (uint32_t)(c & 1)*30720;
            uint32_t nxtB = (uint32_t)((c+1) & 1)*30720;
            if (c + 1 < 8){
                for (int u = t; u < 1536; u += 128){
                    int p = u / 512, rem = u - p*512;
                    int n = rem >> 2, q = rem & 3;
                    cpasync16(sbb + nxtB + p*10240 + n*80 + q*16,
                              W2b + (size_t)p*(4*32768) + (size_t)n*256 + (c+1)*32 + q*8);
                }
                CP_COMMIT();
            }
#pragma unroll
            for (int s=0; s<2; s++){
                uint32_t bf[3][4][2];
#pragma unroll
                for (int p=0; p<3; p++){
#pragma unroll
                    for (int pi=0; pi<2; pi++){
                        uint32_t r4[4];
                        ldm4(r4, sbb + curB + p*10240 + bR2 + pi*(16*20*4) + s*32);
                        bf[p][2*pi][0]=r4[0];   bf[p][2*pi][1]=r4[1];
                        bf[p][2*pi+1][0]=r4[2]; bf[p][2*pi+1][1]=r4[3];
                    }
                }
#pragma unroll
                for (int apl=0; apl<3; apl++){
                    uint32_t af[4][4];
#pragma unroll
                    for (int mi=0; mi<4; mi++)
                        ldm4(af[mi], aR2 + apl*H1PL + (uint32_t)mi*(16*H1PITCH*4) + c*80 + s*32);
                    int nb = (apl==0)?3:((apl==1)?2:1);
#pragma unroll
                    for (int bpl=0; bpl<3; bpl++){
                        if (bpl >= nb) break;
#pragma unroll
                        for (int mi=0; mi<4; mi++)
#pragma unroll
                            for (int ni=0; ni<4; ni++)
                                mma16816(acc[mi*4+ni], af[mi], bf[bpl][ni]);
                    }
                }
            }
            if (c + 1 < 8){ CP_WAIT0(); }
            __syncthreads();
        }
    }

    // ---- w3 dot + per-batch softmax ----
#pragma unroll
    for (int mi=0; mi<4; mi++){
        float pr0 = 0.f, pr1 = 0.f;
#pragma unroll
        for (int ni=0; ni<4; ni++){
            float* d = acc[mi*4+ni];
            int c0 = warpN + ni*8 + (lane&3)*2;
            pr0 += sw3[c0]*lrelu(d[0]) + sw3[c0+1]*lrelu(d[1]);
            pr1 += sw3[c0]*lrelu(d[2]) + sw3[c0+1]*lrelu(d[3]);
        }
        pr0 += __shfl_xor_sync(0xffffffffu, pr0, 1);
        pr0 += __shfl_xor_sync(0xffffffffu, pr0, 2);
        pr1 += __shfl_xor_sync(0xffffffffu, pr1, 1);
        pr1 += __shfl_xor_sync(0xffffffffu, pr1, 2);
        if ((lane & 3) == 0){
            int rl = mi*16 + (lane>>2);
            slog[wid][rl]     = pr0;
            slog[wid][rl + 8] = pr1;
        }
    }
    __syncthreads();
    if (t < 64){
        float v = slog[0][t] + slog[1][t] + slog[2][t] + slog[3][t];
        v = lrelu(v);
        sl[t] = v; sred[t] = v;
    }
    __syncthreads();
    for (int o=32; o>0; o>>=1){ if (t<o) sred[t] = fmaxf(sred[t], sred[t+o]); __syncthreads(); }
    float m = sred[0];
    __syncthreads();
    if (t < 64){ float e = expf(sl[t] - m); sl[t] = e; sred[t] = e; }
    __syncthreads();
    for (int o=32; o>0; o>>=1){ if (t<o) sred[t] += sred[t+o]; __syncthreads(); }
    if (t < 64) g_f[(size_t)z*NNODES + rowBase + t] = sl[t] / sred[0];
}

// ---------------- merged prep + graph ----------------
#define PREP_WK   65536
#define PREP_W1   (PREP_WK + 4*H0W*256)
#define PREP_W2   (PREP_W1 + 131072)
#define PREP_LW   (PREP_W2 + 32768)
#define PREP_X    (PREP_LW + 524288)
#define PREP_QT   (PREP_X + 524288)
#define PREP_BLOCKS 256

__global__ void k_prep_graph(
    const float* __restrict__ Wk, const float* __restrict__ W1,
    const float* __restrict__ W2, const float* __restrict__ LW,
    const float* __restrict__ x, const float* __restrict__ txg,
    const int* __restrict__ row, const int* __restrict__ col,
    const float* __restrict__ ew, float4* __restrict__ xqout)
{
    int t = threadIdx.x;
    if (blockIdx.x >= NBATCH){
        for (int i = (blockIdx.x - NBATCH)*256 + t; i < PREP_QT; i += PREP_BLOCKS*256){
            unsigned short h0,h1,h2;
            if (i < PREP_WK){
                int z = i >> 14, rem = i & 16383, k = rem >> 7, n = rem & 127;
                split3(Wk[i], h0, h1, h2);
                size_t d = (size_t)(z*128 + n)*128 + k;
                g_WkP[d] = __ushort_as_bfloat16(h0);
                g_WkP[4*16384 + d] = __ushort_as_bfloat16(h1);
                g_WkP[8*16384 + d] = __ushort_as_bfloat16(h2);
            } else if (i < PREP_W1){
                int j = i - PREP_WK;
                int z = j / (H0W*256);
                int rem = j - z*(H0W*256);
                int kp = rem >> 8, n = rem & 255;
                const float* w1z = W1 + (size_t)z*131072;
                float v;
                if (kp < 128)      v = w1z[kp*256 + n] + w1z[(kp+256)*256 + n];
                else if (kp < 256) v = w1z[kp*256 + n] - w1z[(kp+128)*256 + n];
                else               v = w1z[(kp+128)*256 + n];
                split3(v, h0, h1, h2);
                size_t d = (size_t)(z*256 + n)*H0W + kp;
                g_W1P[d] = __ushort_as_bfloat16(h0);
                g_W1P[(size_t)4*H0W*256 + d] = __ushort_as_bfloat16(h1);
                g_W1P[(size_t)8*H0W*256 + d] = __ushort_as_bfloat16(h2);
            } else if (i < PREP_W2){
                int j = i - PREP_W1;
                int z = j >> 15, rem = j & 32767, k = rem >> 7, n = rem & 127;
                split3(W2[j], h0, h1, h2);
                size_t d = (size_t)(z*128 + n)*256 + k;
                g_W2P[d] = __ushort_as_bfloat16(h0);
                g_W2P[4*32768 + d] = __ushort_as_bfloat16(h1);
                g_W2P[8*32768 + d] = __ushort_as_bfloat16(h2);
            } else if (i < PREP_LW){
                int j = i - PREP_W2;
                int z = j >> 14, rem = j & 16383, k = rem >> 7, n = rem & 127;
                split3(LW[j], h0, h1, h2);
                size_t d = (size_t)(z*128 + n)*128 + k;
                g_LWP[d] = __ushort_as_bfloat16(h0);
                g_LWP[2*16384 + d] = __ushort_as_bfloat16(h1);
                g_LWP[4*16384 + d] = __ushort_as_bfloat16(h2);
            } else if (i < PREP_X){
                int j = i - PREP_LW;
                split3(x[j], h0, h1, h2);
                g_XP[j] = __ushort_as_bfloat16(h0);
                g_XP[NNODES*HD + j] = __ushort_as_bfloat16(h1);
                g_XP[2*NNODES*HD + j] = __ushort_as_bfloat16(h2);
            } else {
                int j = i - PREP_X;
                g_qt[j] = txg[((j >> 13) << 7) | (j & 127)];
            }
        }
        return;
    }
    extern __shared__ float sh[];
    float* sA   = sh;
    float* sCnt = sh + 4096;
    float* sx   = sh + 8192;
    float* stmp = sh + 16384;
    __shared__ float sdeg[64];
    int b = blockIdx.x;
    for (int i=t; i<4096; i+=256){ sA[i]=0.f; sCnt[i]=0.f; }
    if (t < 64) sdeg[t] = 1.0f;
    __syncthreads();
    const int* er = row + b*EPB;
    const int* ec = col + b*EPB;
    const float* w = ew + b*EPB;
    for (int i=t; i<EPB; i+=256) atomicAdd(&sdeg[ec[i]&63], w[i]);
    __syncthreads();
    if (t < 64) sdeg[t] = rsqrtf(sdeg[t]);
    __syncthreads();
    for (int i=t; i<EPB; i+=256){
        int r = er[i]&63, c = ec[i]&63;
        atomicAdd(&sA[r*64+c], sdeg[r]*w[i]*sdeg[c]);
        atomicAdd(&sCnt[r*64+c], 1.0f);
    }
    if (t < 64){
        atomicAdd(&sA[t*65], sdeg[t]*sdeg[t]);
        atomicAdd(&sCnt[t*65], 1.0f);
    }
    __syncthreads();
    for (int i=t; i<4096; i+=256){ g_A[b*4096+i] = sA[i]; g_Cnt[b*4096+i] = sCnt[i]; }
    float4* sx4 = (float4*)sx;
    const float4* gx4 = (const float4*)(x + (size_t)b*8192);
    for (int i=t; i<2048; i+=256) sx4[i] = gx4[i];
    __syncthreads();
    int tx = t & 31, ty = t >> 5;
    float4* st4 = (float4*)stmp;
    for (int cc=0; cc<8; cc++){
        int c = ty*8+cc;
        float4 acc = make_float4(0.f,0.f,0.f,0.f);
        for (int r=0; r<64; r++){
            float a = sA[r*64+c];
            float4 v = sx4[r*32+tx];
            acc.x += a*v.x; acc.y += a*v.y; acc.z += a*v.z; acc.w += a*v.w;
        }
        st4[c*32+tx] = acc;
    }
    __syncthreads();
    for (int cc=0; cc<8; cc++){
        int c = ty*8+cc;
        float4 acc = make_float4(0.f,0.f,0.f,0.f);
        for (int r=0; r<64; r++){
            float a = sA[r*64+c];
            float4 v = st4[r*32+tx];
            acc.x += a*v.x; acc.y += a*v.y; acc.z += a*v.z; acc.w += a*v.w;
        }
        xqout[(b*64+c)*32 + tx] = acc;
    }
}

// ---------------- fused: edge softmax + agg + linW GEMM + xc + split + hop^2 ----------------
__global__ void __launch_bounds__(128) k_fuse(const float* __restrict__ x, float4* __restrict__ xqout)
{
    extern __shared__ float sh[];
    __shared__ float sf1[64], sf2[64], smx[64], sden[64];
    float* sC  = sh + FSC;
    float* sL  = sh + FSL;
    float* sxc = sh + FXC;
    float* stmp= sh + FTMP;
    int b = blockIdx.x, t = threadIdx.x;
    int wid = t >> 5, lane = t & 31;
    uint32_t sbb;
    asm("{ .reg .u64 tt; cvta.to.shared.u64 tt, %1; cvt.u32.u64 %0, tt; }" : "=r"(sbb) : "l"(sh));

    for (int i=t; i<4096; i+=128) sC[i] = g_Cnt[b*4096+i];
    if (t < 64){ sf1[t] = g_f[b*64+t]; sf2[t] = g_f[NNODES + b*64+t]; }
    __syncthreads();
    for (int i=t; i<4096; i+=128){
        int r = i>>6, c = i&63;
        sL[i] = (sC[i] > 0.f) ? lrelu(sf1[c] + sf2[r]) : -1e30f;
    }
    __syncthreads();
    if (t < 64){
        float m = -1e30f;
        for (int r=0; r<64; r++) m = fmaxf(m, sL[r*64+t]);
        float den = 0.f;
        for (int r=0; r<64; r++){
            float cc = sC[r*64+t];
            if (cc > 0.f) den += cc*expf(sL[r*64+t]-m);
        }
        smx[t] = m; sden[t] = den;
    }
    __syncthreads();
    for (int i=t; i<4096; i+=128){
        int c = i & 63;
        float cc = sC[i];
        float s = (cc > 0.f) ? cc*expf(sL[i]-smx[c])/sden[c] : 0.f;
        sL[i] = s;
        g_S[b*4096+i] = s;
    }
    __syncthreads();

    {
        const float4* X4 = (const float4*)x;
        uint32_t* aggu = (uint32_t*)(sh) + FAGGB/4;
        int tx = lane;
        for (int cc=0; cc<16; cc++){
            int c = wid*16+cc;
            float4 acc = make_float4(0.f,0.f,0.f,0.f);
            for (int r=0; r<64; r++){
                float s = sL[r*64+c];
                float4 v = X4[(b*64+r)*32 + tx];
                acc.x += s*v.x; acc.y += s*v.y; acc.z += s*v.z; acc.w += s*v.w;
            }
            uint32_t pxy0,pxy1,pxy2, pzw0,pzw1,pzw2;
            split2pack(acc.x, acc.y, pxy0, pxy1, pxy2);
            split2pack(acc.z, acc.w, pzw0, pzw1, pzw2);
            int base = c*APITCH + (tx>>3)*20 + (tx&7)*2;
            aggu[base]                    = pxy0;
            aggu[base+1]                  = pzw0;
            aggu[AGPL/4 + base]           = pxy1;
            aggu[AGPL/4 + base+1]         = pzw1;
            aggu[2*(AGPL/4) + base]       = pxy2;
            aggu[2*(AGPL/4) + base+1]     = pzw2;
        }
    }
    __syncthreads();

    int quad = lane >> 3, qi = lane & 7;
    uint32_t aRB = (uint32_t)FAGGB + (uint32_t)((quad&1)*8 + qi)*(APITCH*4) + (quad>>1)*16;
    int warpN = wid * 32;
    uint32_t bRB = (uint32_t)FBBUF + (uint32_t)(warpN + (quad>>1)*8 + qi)*(ROWU*4) + (quad&1)*16;

    for (int h = 0; h < 2; h++){
        float acc[16][4];
#pragma unroll
        for (int i=0;i<16;i++){ acc[i][0]=0.f; acc[i][1]=0.f; acc[i][2]=0.f; acc[i][3]=0.f; }
        for (int cch = 0; cch < 4; cch++){
            for (int u = t; u < 1536; u += 128){
                int p = u / 512, rem = u - p*512;
                int n = rem >> 2, q = rem & 3;
                const __nv_bfloat16* src = g_LWP + (size_t)p*(2*16384) + (size_t)(h*128+n)*128 + cch*32 + q*8;
                cpasync16(sbb + FBBUF + p*(PLUB*4) + n*80 + q*16, src);
            }
            CP_COMMIT(); CP_WAIT0();
            __syncthreads();
#pragma unroll
            for (int s=0; s<2; s++){
                uint32_t bf[3][4][2];
#pragma unroll
                for (int p=0; p<3; p++){
#pragma unroll
                    for (int pi=0; pi<2; pi++){
                        uint32_t r4[4];
                        ldm4(r4, sbb + bRB + p*(PLUB*4) + pi*(16*ROWU*4) + s*32);
                        bf[p][2*pi][0]=r4[0];   bf[p][2*pi][1]=r4[1];
                        bf[p][2*pi+1][0]=r4[2]; bf[p][2*pi+1][1]=r4[3];
                    }
                }
#pragma unroll
                for (int apl=0; apl<3; apl++){
                    uint32_t af[4][4];
#pragma unroll
                    for (int mi=0; mi<4; mi++)
                        ldm4(af[mi], sbb + aRB + apl*AGPL + (uint32_t)mi*(16*APITCH*4) + cch*80 + s*32);
                    int nb = (apl==0)?3:((apl==1)?2:1);
#pragma unroll
                    for (int bpl=0; bpl<3; bpl++){
                        if (bpl >= nb) break;
#pragma unroll
                        for (int mi=0; mi<4; mi++)
#pragma unroll
                            for (int ni=0; ni<4; ni++)
                                mma16816(acc[mi*4+ni], af[mi], bf[bpl][ni]);
                    }
                }
            }
            __syncthreads();
        }
#pragma unroll
        for (int mi=0; mi<4; mi++){
#pragma unroll
            for (int ni=0; ni<4; ni++){
                float* d = acc[mi*4+ni];
                int r0 = mi*16 + (lane>>2);
                int c0 = warpN + ni*8 + (lane&3)*2;
#pragma unroll
                for (int qi2=0; qi2<2; qi2++){
                    int row = r0 + qi2*8;
                    float xv0 = x[(size_t)(b*64+row)*128 + c0];
                    float xv1 = x[(size_t)(b*64+row)*128 + c0 + 1];
                    float v0 = lrelu(xv0 + d[qi2*2]);
                    float v1 = lrelu(xv1 + d[qi2*2+1]);
                    if (h == 0){
                        sxc[row*128 + c0]     = v0;
                        sxc[row*128 + c0 + 1] = v1;
                    } else {
                        sxc[row*128 + c0]     = 0.5f*(sxc[row*128 + c0] + v0);
                        sxc[row*128 + c0 + 1] = 0.5f*(sxc[row*128 + c0 + 1] + v1);
                    }
                }
            }
        }
        __syncthreads();
    }

    for (int i=t; i<4096; i+=128){
        int idx2 = i*2;
        size_t gi = (size_t)b*8192 + idx2;
        float v0 = sxc[idx2], v1 = sxc[idx2+1];
        uint32_t q0,q1,q2;
        split2pack(v0, v1, q0, q1, q2);
        *(uint32_t*)(g_xcP + gi)                = q0;
        *(uint32_t*)(g_xcP + NNODES*HD + gi)    = q1;
        *(uint32_t*)(g_xcP + 2*NNODES*HD + gi)  = q2;
    }
    for (int i=t; i<4096; i+=128) sC[i] = g_A[b*4096+i];
    __syncthreads();
    {
        const float4* sx4 = (const float4*)sxc;
        float4* st4 = (float4*)stmp;
        int tx = lane;
        for (int cc=0; cc<16; cc++){
            int c = wid*16+cc;
            float4 acc = make_float4(0.f,0.f,0.f,0.f);
            for (int r=0; r<64; r++){
                float a = sC[r*64+c];
                float4 v = sx4[r*32 + tx];
                acc.x += a*v.x; acc.y += a*v.y; acc.z += a*v.z; acc.w += a*v.w;
            }
            st4[c*32+tx] = acc;
        }
        __syncthreads();
        for (int cc=0; cc<16; cc++){
            int c = wid*16+cc;
            float4 acc = make_float4(0.f,0.f,0.f,0.f);
            for (int r=0; r<64; r++){
                float a = sC[r*64+c];
                float4 v = st4[r*32 + tx];
                acc.x += a*v.x; acc.y += a*v.y; acc.z += a*v.z; acc.w += a*v.w;
            }
            xqout[(b*64+c)*32 + tx] = acc;
        }
    }
}

// ---------------- score softmax + top-k + outputs + A2 ----------------
__global__ void k_topkA2(const float* __restrict__ x, float* __restrict__ out){
    __shared__ float sA[NPG*NPG];
    __shared__ float sS[NPG*NPG];
    __shared__ float sU[NPG*KK];
    __shared__ float s[64];
    __shared__ float red[64];
    __shared__ int lp[KK];
    int b = blockIdx.x, t = threadIdx.x;
    if (t < 64){ float v = g_f[b*64+t] + g_f[NNODES + b*64+t]; s[t] = v; red[t] = v; }
    __syncthreads();
    for (int o=32; o>0; o>>=1){ if (t<o) red[t] = fmaxf(red[t], red[t+o]); __syncthreads(); }
    float m = red[0];
    __syncthreads();
    if (t < 64){ float e = expf(s[t] - m); s[t] = e; red[t] = e; }
    __syncthreads();
    for (int o=32; o>0; o>>=1){ if (t<o) red[t] += red[t+o]; __syncthreads(); }
    float den = red[0];
    __syncthreads();
    if (t < 64) s[t] = s[t] / den;
    __syncthreads();
    if (t < 64){
        float v = s[t];
        int rank = 0;
        for (int j=0; j<64; j++){
            float u = s[j];
            rank += (u > v) || (u == v && j < t);
        }
        if (rank < KK){
            lp[rank] = t;
            out[OFF_B + b*KK+rank] = (float)b;
            out[OFF_P + b*KK+rank] = (float)(b*64+t);
        }
    }
    __syncthreads();
    {
        const float4* x4 = (const float4*)x;
        float4* o4 = (float4*)out;
        for (int i=t; i<KK*32; i+=256){
            int r = i >> 5, f = i & 31;
            int p = lp[r];
            float sc = s[p];
            float4 v = x4[(b*64+p)*32 + f];
            o4[(size_t)(b*KK+r)*32 + f] = make_float4(v.x*sc, v.y*sc, v.z*sc, v.w*sc);
        }
    }
    {
        float4 z4 = make_float4(0.f,0.f,0.f,0.f);
        float4* a4 = (float4*)(out + OFF_A2);
        for (int idx=t; idx<KK*NK4; idx+=256){
            int i2 = idx / NK4, c4 = idx - i2*NK4;
            a4[(size_t)(b*KK+i2)*NK4 + c4] = z4;
        }
    }
    for (int i=t; i<NPG*NPG; i+=256){ sA[i] = g_A[b*NPG*NPG+i]; sS[i] = g_S[b*NPG*NPG+i]; }
    __syncthreads();
    for (int idx=t; idx<NPG*KK; idx+=256){
        int r = idx / KK, j = idx - r*KK;
        int pj = lp[j];
        float acc = 0.f;
        for (int c=0; c<NPG; c++) acc += sA[r*NPG+c]*sS[c*NPG+pj];
        sU[idx] = acc;
    }
    __syncthreads();
    for (int idx=t; idx<KK*KK; idx+=256){
        int i2 = idx / KK, j = idx - i2*KK;
        int pi = lp[i2];
        float acc = 0.f;
        for (int r=0; r<NPG; r++) acc += sS[r*NPG+pi]*sU[r*KK+j];
        float v = (i2 == j) ? 1.0f : acc;
        out[(size_t)OFF_A2 + (size_t)(b*KK+i2)*NK + (b*KK+j)] = v;
    }
}

// ---------------- host ----------------
extern "C" void kernel_launch(void* const* d_in, const int* in_sizes, int n_in,
                              void* d_out, int out_size)
{
    (void)in_sizes; (void)n_in; (void)out_size;
    const float* x    = (const float*)d_in[0];
    const int*   ei   = (const int*)  d_in[1];
    const float* ew   = (const float*)d_in[2];
    const float* txg  = (const float*)d_in[3];
    const float* Wk   = (const float*)d_in[5];
    const float* W1   = (const float*)d_in[6];
    const float* W2   = (const float*)d_in[7];
    const float* W3   = (const float*)d_in[8];
    const float* linW = (const float*)d_in[9];
    float* out = (float*)d_out;
    const int* row = ei;
    const int* col = ei + NE;

    cudaFuncSetAttribute(k_att,        cudaFuncAttributeMaxDynamicSharedMemorySize, ATT_SMEM);
    cudaFuncSetAttribute(k_prep_graph, cudaFuncAttributeMaxDynamicSharedMemorySize, 98304);
    cudaFuncSetAttribute(k_fuse,       cudaFuncAttributeMaxDynamicSharedMemorySize, FUSE_SMEM);

    float *p_xq,*p_qt;
    __nv_bfloat16 *p_XP,*p_xcP;
    cudaGetSymbolAddress((void**)&p_xq,   g_xq);
    cudaGetSymbolAddress((void**)&p_qt,   g_qt);
    cudaGetSymbolAddress((void**)&p_XP,   g_XP);
    cudaGetSymbolAddress((void**)&p_xcP,  g_xcP);

    // 1. prep + graph build + hop^2(x)
    k_prep_graph<<<NBATCH + PREP_BLOCKS, 256, 98304>>>(Wk, W1, W2, linW, x, txg,
                                                       row, col, ew, (float4*)p_xq);
    // 2. f1 = att(x, xq); f2 = att(x, qt)   (fully fused)
    k_att<<<dim3(1,64,2),128,ATT_SMEM>>>(0, p_XP, p_xq, p_qt, W3);
    // 3. fused edge softmax + agg + linW GEMM + xc + split + hop^2
    k_fuse<<<NBATCH,128,FUSE_SMEM>>>(x, (float4*)p_xq);
    // 4. g1 = att(xc, xq2); g2 = att(xc, qt)
    k_att<<<dim3(1,64,2),128,ATT_SMEM>>>(2, p_xcP, p_xq, p_qt, W3);
    // 5. score softmax + top-k + outputs + A2
    k_topkA2<<<NBATCH,256>>>(x, out);
}

// round 17
// speedup vs baseline: 1.3411x; 1.3411x over previous
#include <cuda_runtime.h>
#include <cuda_bf16.h>
#include <cstdint>

// ---------------- problem constants ----------------
#define NNODES 4096
#define NBATCH 64
#define NPG    64
#define HD     128
#define HD4    32
#define NE     131072
#define EPB    2048
#define KK     52
#define NK     3328
#define NK4    (NK/4)

#define LEN_X  (NK*HD)
#define OFF_A2 (LEN_X)
#define OFF_B  (OFF_A2 + NK*NK)
#define OFF_P  (OFF_B + NK)

// 2 planes per operand (2-way bf16 split)
#define ROWU 20
#define PLUA (64*ROWU)           // 1280 u32
#define PLUB (128*ROWU)          // 2560 u32
#define BUFU (2*PLUA + 2*PLUB)   // 7680 u32
#define GSMEM (2*BUFU*4)         // 61440 bytes

#define H0W 384

// k_fuse smem layout
#define FSC   0
#define FSL   4096
#define FXC   8192
#define FTMP  16384
#define FAGGB 98304
#define APITCH 84
#define AGPL  (64*APITCH*4)      // 21504 B per plane
#define FBBUF (FAGGB + 2*AGPL)   // 141312
#define FUSE_SMEM (FBBUF + 2*PLUB*4)   // 161792 B

// ---------------- scratch ----------------
__device__ float g_A[NBATCH*NPG*NPG];
__device__ float g_Cnt[NBATCH*NPG*NPG];
__device__ float g_S[NBATCH*NPG*NPG];
__device__ float g_xq[NNODES*HD];
__device__ float g_qt[NNODES*HD];
__device__ float g_f[2*NNODES];

__device__ __align__(16) __nv_bfloat16 g_XP  [2*NNODES*HD];
__device__ __align__(16) __nv_bfloat16 g_xcP [2*NNODES*HD];
__device__ __align__(16) __nv_bfloat16 g_WkP [2*4*128*128];
__device__ __align__(16) __nv_bfloat16 g_W1P [2*4*256*H0W];
__device__ __align__(16) __nv_bfloat16 g_W2P [2*4*128*256];
__device__ __align__(16) __nv_bfloat16 g_LWP [2*2*128*128];
__device__ __align__(16) __nv_bfloat16 g_h0P [2*2*NNODES*H0W];
__device__ __align__(16) __nv_bfloat16 g_h1P [2*2*NNODES*256];

__device__ __forceinline__ float lrelu(float v){ return v > 0.f ? v : 0.01f*v; }

// 2-way bf16 split
__device__ __forceinline__ void split2(float a, unsigned short& h0, unsigned short& h1){
    __nv_bfloat16 b0 = __float2bfloat16(a); float r1 = a - __bfloat162float(b0);
    __nv_bfloat16 b1 = __float2bfloat16(r1);
    h0 = __bfloat16_as_ushort(b0);
    h1 = __bfloat16_as_ushort(b1);
}
__device__ __forceinline__ void split2pack(float a, float b, uint32_t& p0, uint32_t& p1){
    unsigned short a0,a1,b0,b1;
    split2(a, a0, a1);
    split2(b, b0, b1);
    p0 = (uint32_t)a0 | ((uint32_t)b0 << 16);
    p1 = (uint32_t)a1 | ((uint32_t)b1 << 16);
}

__device__ __forceinline__ void mma16816(float* d, const uint32_t* a, const uint32_t* b){
    asm volatile(
        "mma.sync.aligned.m16n8k16.row.col.f32.bf16.bf16.f32 "
        "{%0,%1,%2,%3}, {%4,%5,%6,%7}, {%8,%9}, {%0,%1,%2,%3};"
        : "+f"(d[0]), "+f"(d[1]), "+f"(d[2]), "+f"(d[3])
        : "r"(a[0]), "r"(a[1]), "r"(a[2]), "r"(a[3]), "r"(b[0]), "r"(b[1]));
}

__device__ __forceinline__ void ldm4(uint32_t* r, uint32_t addr){
    asm volatile("ldmatrix.sync.aligned.m8n8.x4.shared.b16 {%0,%1,%2,%3}, [%4];"
        : "=r"(r[0]), "=r"(r[1]), "=r"(r[2]), "=r"(r[3]) : "r"(addr));
}

__device__ __forceinline__ void cpasync16(uint32_t dst, const void* src){
    asm volatile("cp.async.ca.shared.global [%0], [%1], 16;" :: "r"(dst), "l"(src) : "memory");
}
#define CP_COMMIT() asm volatile("cp.async.commit_group;" ::: "memory")
#define CP_WAIT0()  asm volatile("cp.async.wait_group 0;" ::: "memory")

// ---------------- cp.async fill (A 64 rows, B 128 rows, 32 k, 128 threads, 2 planes) ----------------
#define ISSUECOPY(AP, aZ, aP, BP, bZ, bP, KTOT, K0, BUFB)                                  \
    _Pragma("unroll")                                                                      \
    for (int p=0; p<2; p++){                                                               \
        _Pragma("unroll")                                                                  \
        for (int it=0; it<2; it++){                                                        \
            int e = t + it*128;                                                            \
            int ar = e >> 2, aq = e & 3;                                                   \
            const __nv_bfloat16* as = (AP) + (size_t)p*(aP) + (size_t)z*(aZ)               \
                + (size_t)(rowBase+ar)*(KTOT) + (K0) + aq*8;                               \
            cpasync16(sbb + (BUFB) + p*(PLUA*4) + ar*80 + aq*16, as);                      \
        }                                                                                  \
        _Pragma("unroll")                                                                  \
        for (int it=0; it<4; it++){                                                        \
            int e = t + it*128;                                                            \
            int br = e >> 2, bq = e & 3;                                                   \
            const __nv_bfloat16* bs = (BP) + (size_t)p*(bP) + (size_t)z*(bZ)               \
                + (size_t)(colBase+br)*(KTOT) + (K0) + bq*8;                               \
            cpasync16(sbb + (BUFB) + (2*PLUA + p*PLUB)*4 + br*80 + bq*16, bs);             \
        }                                                                                  \
    }                                                                                      \
    CP_COMMIT();

// MMA stage: products a0b0, a0b1, a1b0
#define MMACHUNK(BUFB)                                                                     \
    _Pragma("unroll")                                                                      \
    for (int s=0; s<2; s++){                                                               \
        uint32_t bf[2][4][2];                                                              \
        _Pragma("unroll")                                                                  \
        for (int p=0; p<2; p++){                                                           \
            _Pragma("unroll")                                                              \
            for (int pi=0; pi<2; pi++){                                                    \
                uint32_t r4[4];                                                            \
                ldm4(r4, sbb + (BUFB) + (2*PLUA + p*PLUB)*4 + bRowBase + pi*(16*ROWU*4) + s*32); \
                bf[p][2*pi][0]=r4[0];   bf[p][2*pi][1]=r4[1];                              \
                bf[p][2*pi+1][0]=r4[2]; bf[p][2*pi+1][1]=r4[3];                            \
            }                                                                              \
        }                                                                                  \
        _Pragma("unroll")                                                                  \
        for (int apl=0; apl<2; apl++){                                                     \
            uint32_t af[4][4];                                                             \
            _Pragma("unroll")                                                              \
            for (int mi=0; mi<4; mi++)                                                     \
                ldm4(af[mi], sbb + (BUFB) + apl*(PLUA*4) + aRowBase + mi*(16*ROWU*4) + s*32);\
            int nb = (apl==0)?2:1;                                                         \
            _Pragma("unroll")                                                              \
            for (int bpl=0; bpl<2; bpl++){                                                 \
                if (bpl >= nb) break;                                                      \
                _Pragma("unroll")                                                          \
                for (int mi=0; mi<4; mi++)                                                 \
                    _Pragma("unroll")                                                      \
                    for (int ni=0; ni<4; ni++)                                             \
                        mma16816(acc[mi*4+ni], af[mi], bf[bpl][ni]);                       \
            }                                                                              \
        }                                                                                  \
    }

#define GEMM_MAINLOOP(AP, aZ, aP, BP, bZ, bP, KTOT)                                        \
    int chunks = (KTOT) >> 5;                                                              \
    uint32_t sbb;                                                                          \
    asm("{ .reg .u64 tt; cvta.to.shared.u64 tt, %1; cvt.u32.u64 %0, tt; }" : "=r"(sbb) : "l"(smu)); \
    int quad = lane >> 3, qi = lane & 7;                                                   \
    uint32_t aRowBase = (uint32_t)((quad&1)*8 + qi)*(ROWU*4) + (quad>>1)*16;               \
    uint32_t bRowBase = (uint32_t)(warpN + (quad>>1)*8 + qi)*(ROWU*4) + (quad&1)*16;       \
    ISSUECOPY(AP, aZ, aP, BP, bZ, bP, KTOT, 0, 0)                                          \
    CP_WAIT0();                                                                            \
    __syncthreads();                                                                       \
    for (int c = 0; c < chunks; c++){                                                      \
        uint32_t curB = (uint32_t)(c & 1)*(BUFU*4);                                        \
        uint32_t nxtB = (uint32_t)((c + 1) & 1)*(BUFU*4);                                  \
        if (c + 1 < chunks){ ISSUECOPY(AP, aZ, aP, BP, bZ, bP, KTOT, (c+1) << 5, nxtB) }   \
        MMACHUNK(curB)                                                                     \
        if (c + 1 < chunks){ CP_WAIT0(); }                                                 \
        __syncthreads();                                                                   \
    }

// ---------------- pre-split GEMM (EPI 2=lrelu+split planes, 3=h0 concat [a,q,a*q]) ----------------
template<int EPI>
__global__ void __launch_bounds__(128) k_pgemm(
    const __nv_bfloat16* __restrict__ AP, long long aZ, long long aP,
    const __nv_bfloat16* __restrict__ BP, long long bZ, long long bP,
    int Ktot, int Nc,
    __nv_bfloat16* __restrict__ OP, long long oZ, long long oP,
    const float* __restrict__ q0, const float* __restrict__ q1)
{
    extern __shared__ uint32_t smu[];
    int t = threadIdx.x, wid = t >> 5, lane = t & 31;
    int z = blockIdx.z;
    int rowBase = blockIdx.y * 64;
    int colBase = blockIdx.x * 128;
    int warpN = wid * 32;

    float acc[16][4];
#pragma unroll
    for (int i=0;i<16;i++){ acc[i][0]=0.f; acc[i][1]=0.f; acc[i][2]=0.f; acc[i][3]=0.f; }

    GEMM_MAINLOOP(AP, aZ, aP, BP, bZ, bP, Ktot)

#pragma unroll
    for (int mi=0; mi<4; mi++){
#pragma unroll
        for (int ni=0; ni<4; ni++){
            float* d = acc[mi*4+ni];
            int r0 = rowBase + mi*16 + (lane>>2);
            int c0 = colBase + warpN + ni*8 + (lane&3)*2;
            if (EPI == 2){
#pragma unroll
                for (int qi2=0; qi2<2; qi2++){
                    int row = r0 + qi2*8;
                    float da = lrelu(d[qi2*2]), db = lrelu(d[qi2*2+1]);
                    uint32_t p0,p1;
                    split2pack(da, db, p0, p1);
                    size_t off = (size_t)z*oZ + (size_t)row*Nc + c0;
                    *(uint32_t*)(OP + off)        = p0;
                    *(uint32_t*)(OP + oP + off)   = p1;
                }
            } else {   // EPI == 3
                const float* q = z ? q1 : q0;
#pragma unroll
                for (int qi2=0; qi2<2; qi2++){
                    int row = r0 + qi2*8;
                    float av = d[qi2*2], bv = d[qi2*2+1];
                    float qa = q[(size_t)row*128 + c0];
                    float qb = q[(size_t)row*128 + c0 + 1];
                    float sa[3] = {av, qa, av*qa};
                    float sb[3] = {bv, qb, bv*qb};
#pragma unroll
                    for (int sec=0; sec<3; sec++){
                        uint32_t p0,p1;
                        split2pack(sa[sec], sb[sec], p0, p1);
                        size_t off = (size_t)z*oZ + (size_t)row*H0W + sec*128 + c0;
                        *(uint32_t*)(OP + off)        = p0;
                        *(uint32_t*)(OP + oP + off)   = p1;
                    }
                }
            }
        }
    }
}

// ---------------- W2 GEMM + W3 dot + per-batch softmax ----------------
__global__ void __launch_bounds__(128) k_w2s(const float* __restrict__ W3, int base)
{
    extern __shared__ uint32_t smu[];
    __shared__ float sw3[128];
    __shared__ float slog[4][64];
    __shared__ float sl[64];
    __shared__ float sred[64];
    int t = threadIdx.x, wid = t >> 5, lane = t & 31;
    int z = blockIdx.z;
    int rowBase = blockIdx.y * 64;
    int colBase = 0;
    int warpN = wid * 32;

    if (t < 128) sw3[t] = W3[(size_t)(base+z)*128 + t];

    float acc[16][4];
#pragma unroll
    for (int i=0;i<16;i++){ acc[i][0]=0.f; acc[i][1]=0.f; acc[i][2]=0.f; acc[i][3]=0.f; }

    GEMM_MAINLOOP(g_h1P, (long long)NNODES*256, 2LL*NNODES*256,
                  g_W2P + (size_t)base*32768, 32768LL, 4LL*32768, 256)

#pragma unroll
    for (int mi=0; mi<4; mi++){
        float pr0 = 0.f, pr1 = 0.f;
#pragma unroll
        for (int ni=0; ni<4; ni++){
            float* d = acc[mi*4+ni];
            int c0 = warpN + ni*8 + (lane&3)*2;
            pr0 += sw3[c0]*lrelu(d[0]) + sw3[c0+1]*lrelu(d[1]);
            pr1 += sw3[c0]*lrelu(d[2]) + sw3[c0+1]*lrelu(d[3]);
        }
        pr0 += __shfl_xor_sync(0xffffffffu, pr0, 1);
        pr0 += __shfl_xor_sync(0xffffffffu, pr0, 2);
        pr1 += __shfl_xor_sync(0xffffffffu, pr1, 1);
        pr1 += __shfl_xor_sync(0xffffffffu, pr1, 2);
        if ((lane & 3) == 0){
            int rl = mi*16 + (lane>>2);
            slog[wid][rl]     = pr0;
            slog[wid][rl + 8] = pr1;
        }
    }
    __syncthreads();
    if (t < 64){
        float v = slog[0][t] + slog[1][t] + slog[2][t] + slog[3][t];
        v = lrelu(v);
        sl[t] = v; sred[t] = v;
    }
    __syncthreads();
    for (int o=32; o>0; o>>=1){ if (t<o) sred[t] = fmaxf(sred[t], sred[t+o]); __syncthreads(); }
    float m = sred[0];
    __syncthreads();
    if (t < 64){ float e = expf(sl[t] - m); sl[t] = e; sred[t] = e; }
    __syncthreads();
    for (int o=32; o>0; o>>=1){ if (t<o) sred[t] += sred[t+o]; __syncthreads(); }
    if (t < 64) g_f[(size_t)z*NNODES + rowBase + t] = sl[t] / sred[0];
}

// ---------------- merged prep + graph ----------------
#define PREP_WK   65536
#define PREP_W1   (PREP_WK + 4*H0W*256)
#define PREP_W2   (PREP_W1 + 131072)
#define PREP_LW   (PREP_W2 + 32768)
#define PREP_X    (PREP_LW + 524288)
#define PREP_QT   (PREP_X + 524288)
#define PREP_BLOCKS 256

__global__ void k_prep_graph(
    const float* __restrict__ Wk, const float* __restrict__ W1,
    const float* __restrict__ W2, const float* __restrict__ LW,
    const float* __restrict__ x, const float* __restrict__ txg,
    const int* __restrict__ row, const int* __restrict__ col,
    const float* __restrict__ ew, float4* __restrict__ xqout)
{
    int t = threadIdx.x;
    if (blockIdx.x >= NBATCH){
        for (int i = (blockIdx.x - NBATCH)*256 + t; i < PREP_QT; i += PREP_BLOCKS*256){
            unsigned short h0,h1;
            if (i < PREP_WK){
                int z = i >> 14, rem = i & 16383, k = rem >> 7, n = rem & 127;
                split2(Wk[i], h0, h1);
                size_t d = (size_t)(z*128 + n)*128 + k;
                g_WkP[d] = __ushort_as_bfloat16(h0);
                g_WkP[4*16384 + d] = __ushort_as_bfloat16(h1);
            } else if (i < PREP_W1){
                int j = i - PREP_WK;
                int z = j / (H0W*256);
                int rem = j - z*(H0W*256);
                int kp = rem >> 8, n = rem & 255;
                const float* w1z = W1 + (size_t)z*131072;
                float v;
                if (kp < 128)      v = w1z[kp*256 + n] + w1z[(kp+256)*256 + n];
                else if (kp < 256) v = w1z[kp*256 + n] - w1z[(kp+128)*256 + n];
                else               v = w1z[(kp+128)*256 + n];
                split2(v, h0, h1);
                size_t d = (size_t)(z*256 + n)*H0W + kp;
                g_W1P[d] = __ushort_as_bfloat16(h0);
                g_W1P[(size_t)4*H0W*256 + d] = __ushort_as_bfloat16(h1);
            } else if (i < PREP_W2){
                int j = i - PREP_W1;
                int z = j >> 15, rem = j & 32767, k = rem >> 7, n = rem & 127;
                split2(W2[j], h0, h1);
                size_t d = (size_t)(z*128 + n)*256 + k;
                g_W2P[d] = __ushort_as_bfloat16(h0);
                g_W2P[4*32768 + d] = __ushort_as_bfloat16(h1);
            } else if (i < PREP_LW){
                int j = i - PREP_W2;
                int z = j >> 14, rem = j & 16383, k = rem >> 7, n = rem & 127;
                split2(LW[j], h0, h1);
                size_t d = (size_t)(z*128 + n)*128 + k;
                g_LWP[d] = __ushort_as_bfloat16(h0);
                g_LWP[2*16384 + d] = __ushort_as_bfloat16(h1);
            } else if (i < PREP_X){
                int j = i - PREP_LW;
                split2(x[j], h0, h1);
                g_XP[j] = __ushort_as_bfloat16(h0);
                g_XP[NNODES*HD + j] = __ushort_as_bfloat16(h1);
            } else {
                int j = i - PREP_X;
                g_qt[j] = txg[((j >> 13) << 7) | (j & 127)];
            }
        }
        return;
    }
    extern __shared__ float sh[];
    float* sA   = sh;
    float* sCnt = sh + 4096;
    float* sx   = sh + 8192;
    float* stmp = sh + 16384;
    __shared__ float sdeg[64];
    int b = blockIdx.x;
    for (int i=t; i<4096; i+=256){ sA[i]=0.f; sCnt[i]=0.f; }
    if (t < 64) sdeg[t] = 1.0f;
    __syncthreads();
    const int* er = row + b*EPB;
    const int* ec = col + b*EPB;
    const float* w = ew + b*EPB;
    for (int i=t; i<EPB; i+=256) atomicAdd(&sdeg[ec[i]&63], w[i]);
    __syncthreads();
    if (t < 64) sdeg[t] = rsqrtf(sdeg[t]);
    __syncthreads();
    for (int i=t; i<EPB; i+=256){
        int r = er[i]&63, c = ec[i]&63;
        atomicAdd(&sA[r*64+c], sdeg[r]*w[i]*sdeg[c]);
        atomicAdd(&sCnt[r*64+c], 1.0f);
    }
    if (t < 64){
        atomicAdd(&sA[t*65], sdeg[t]*sdeg[t]);
        atomicAdd(&sCnt[t*65], 1.0f);
    }
    __syncthreads();
    for (int i=t; i<4096; i+=256){ g_A[b*4096+i] = sA[i]; g_Cnt[b*4096+i] = sCnt[i]; }
    float4* sx4 = (float4*)sx;
    const float4* gx4 = (const float4*)(x + (size_t)b*8192);
    for (int i=t; i<2048; i+=256) sx4[i] = gx4[i];
    __syncthreads();
    int tx = t & 31, ty = t >> 5;
    float4* st4 = (float4*)stmp;
    for (int cc=0; cc<8; cc++){
        int c = ty*8+cc;
        float4 acc = make_float4(0.f,0.f,0.f,0.f);
        for (int r=0; r<64; r++){
            float a = sA[r*64+c];
            float4 v = sx4[r*32+tx];
            acc.x += a*v.x; acc.y += a*v.y; acc.z += a*v.z; acc.w += a*v.w;
        }
        st4[c*32+tx] = acc;
    }
    __syncthreads();
    for (int cc=0; cc<8; cc++){
        int c = ty*8+cc;
        float4 acc = make_float4(0.f,0.f,0.f,0.f);
        for (int r=0; r<64; r++){
            float a = sA[r*64+c];
            float4 v = st4[r*32+tx];
            acc.x += a*v.x; acc.y += a*v.y; acc.z += a*v.z; acc.w += a*v.w;
        }
        xqout[(b*64+c)*32 + tx] = acc;
    }
}

// ---------------- fused: edge softmax + agg + linW GEMM + xc + split + hop^2 ----------------
__global__ void __launch_bounds__(128) k_fuse(const float* __restrict__ x, float4* __restrict__ xqout)
{
    extern __shared__ float sh[];
    __shared__ float sf1[64], sf2[64], smx[64], sden[64];
    float* sC  = sh + FSC;
    float* sL  = sh + FSL;
    float* sxc = sh + FXC;
    float* stmp= sh + FTMP;
    int b = blockIdx.x, t = threadIdx.x;
    int wid = t >> 5, lane = t & 31;
    uint32_t sbb;
    asm("{ .reg .u64 tt; cvta.to.shared.u64 tt, %1; cvt.u32.u64 %0, tt; }" : "=r"(sbb) : "l"(sh));

    for (int i=t; i<4096; i+=128) sC[i] = g_Cnt[b*4096+i];
    if (t < 64){ sf1[t] = g_f[b*64+t]; sf2[t] = g_f[NNODES + b*64+t]; }
    __syncthreads();
    for (int i=t; i<4096; i+=128){
        int r = i>>6, c = i&63;
        sL[i] = (sC[i] > 0.f) ? lrelu(sf1[c] + sf2[r]) : -1e30f;
    }
    __syncthreads();
    if (t < 64){
        float m = -1e30f;
        for (int r=0; r<64; r++) m = fmaxf(m, sL[r*64+t]);
        float den = 0.f;
        for (int r=0; r<64; r++){
            float cc = sC[r*64+t];
            if (cc > 0.f) den += cc*expf(sL[r*64+t]-m);
        }
        smx[t] = m; sden[t] = den;
    }
    __syncthreads();
    for (int i=t; i<4096; i+=128){
        int c = i & 63;
        float cc = sC[i];
        float s = (cc > 0.f) ? cc*expf(sL[i]-smx[c])/sden[c] : 0.f;
        sL[i] = s;
        g_S[b*4096+i] = s;
    }
    __syncthreads();

    {
        const float4* X4 = (const float4*)x;
        uint32_t* aggu = (uint32_t*)(sh) + FAGGB/4;
        int tx = lane;
        for (int cc=0; cc<16; cc++){
            int c = wid*16+cc;
            float4 acc = make_float4(0.f,0.f,0.f,0.f);
            for (int r=0; r<64; r++){
                float s = sL[r*64+c];
                float4 v = X4[(b*64+r)*32 + tx];
                acc.x += s*v.x; acc.y += s*v.y; acc.z += s*v.z; acc.w += s*v.w;
            }
            uint32_t pxy0,pxy1, pzw0,pzw1;
            split2pack(acc.x, acc.y, pxy0, pxy1);
            split2pack(acc.z, acc.w, pzw0, pzw1);
            int base = c*APITCH + (tx>>3)*20 + (tx&7)*2;
            aggu[base]              = pxy0;
            aggu[base+1]            = pzw0;
            aggu[AGPL/4 + base]     = pxy1;
            aggu[AGPL/4 + base+1]   = pzw1;
        }
    }
    __syncthreads();

    int quad = lane >> 3, qi = lane & 7;
    uint32_t aRB = (uint32_t)FAGGB + (uint32_t)((quad&1)*8 + qi)*(APITCH*4) + (quad>>1)*16;
    int warpN = wid * 32;
    uint32_t bRB = (uint32_t)FBBUF + (uint32_t)(warpN + (quad>>1)*8 + qi)*(ROWU*4) + (quad&1)*16;

    for (int h = 0; h < 2; h++){
        float acc[16][4];
#pragma unroll
        for (int i=0;i<16;i++){ acc[i][0]=0.f; acc[i][1]=0.f; acc[i][2]=0.f; acc[i][3]=0.f; }
        for (int cch = 0; cch < 4; cch++){
            // copy B chunk: 2 planes x 128 rows x 4 quads = 1024 16B units
            for (int u = t; u < 1024; u += 128){
                int p = u >> 9, rem = u & 511;
                int n = rem >> 2, q = rem & 3;
                const __nv_bfloat16* src = g_LWP + (size_t)p*(2*16384) + (size_t)(h*128+n)*128 + cch*32 + q*8;
                cpasync16(sbb + FBBUF + p*(PLUB*4) + n*80 + q*16, src);
            }
            CP_COMMIT(); CP_WAIT0();
            __syncthreads();
#pragma unroll
            for (int s=0; s<2; s++){
                uint32_t bf[2][4][2];
#pragma unroll
                for (int p=0; p<2; p++){
#pragma unroll
                    for (int pi=0; pi<2; pi++){
                        uint32_t r4[4];
                        ldm4(r4, sbb + bRB + p*(PLUB*4) + pi*(16*ROWU*4) + s*32);
                        bf[p][2*pi][0]=r4[0];   bf[p][2*pi][1]=r4[1];
                        bf[p][2*pi+1][0]=r4[2]; bf[p][2*pi+1][1]=r4[3];
                    }
                }
#pragma unroll
                for (int apl=0; apl<2; apl++){
                    uint32_t af[4][4];
#pragma unroll
                    for (int mi=0; mi<4; mi++)
                        ldm4(af[mi], sbb + aRB + apl*AGPL + (uint32_t)mi*(16*APITCH*4) + cch*80 + s*32);
                    int nb = (apl==0)?2:1;
#pragma unroll
                    for (int bpl=0; bpl<2; bpl++){
                        if (bpl >= nb) break;
#pragma unroll
                        for (int mi=0; mi<4; mi++)
#pragma unroll
                            for (int ni=0; ni<4; ni++)
                                mma16816(acc[mi*4+ni], af[mi], bf[bpl][ni]);
                    }
                }
            }
            __syncthreads();
        }
#pragma unroll
        for (int mi=0; mi<4; mi++){
#pragma unroll
            for (int ni=0; ni<4; ni++){
                float* d = acc[mi*4+ni];
                int r0 = mi*16 + (lane>>2);
                int c0 = warpN + ni*8 + (lane&3)*2;
#pragma unroll
                for (int qi2=0; qi2<2; qi2++){
                    int row = r0 + qi2*8;
                    float xv0 = x[(size_t)(b*64+row)*128 + c0];
                    float xv1 = x[(size_t)(b*64+row)*128 + c0 + 1];
                    float v0 = lrelu(xv0 + d[qi2*2]);
                    float v1 = lrelu(xv1 + d[qi2*2+1]);
                    if (h == 0){
                        sxc[row*128 + c0]     = v0;
                        sxc[row*128 + c0 + 1] = v1;
                    } else {
                        sxc[row*128 + c0]     = 0.5f*(sxc[row*128 + c0] + v0);
                        sxc[row*128 + c0 + 1] = 0.5f*(sxc[row*128 + c0 + 1] + v1);
                    }
                }
            }
        }
        __syncthreads();
    }

    for (int i=t; i<4096; i+=128){
        int idx2 = i*2;
        size_t gi = (size_t)b*8192 + idx2;
        float v0 = sxc[idx2], v1 = sxc[idx2+1];
        uint32_t q0,q1;
        split2pack(v0, v1, q0, q1);
        *(uint32_t*)(g_xcP + gi)             = q0;
        *(uint32_t*)(g_xcP + NNODES*HD + gi) = q1;
    }
    for (int i=t; i<4096; i+=128) sC[i] = g_A[b*4096+i];
    __syncthreads();
    {
        const float4* sx4 = (const float4*)sxc;
        float4* st4 = (float4*)stmp;
        int tx = lane;
        for (int cc=0; cc<16; cc++){
            int c = wid*16+cc;
            float4 acc = make_float4(0.f,0.f,0.f,0.f);
            for (int r=0; r<64; r++){
                float a = sC[r*64+c];
                float4 v = sx4[r*32 + tx];
                acc.x += a*v.x; acc.y += a*v.y; acc.z += a*v.z; acc.w += a*v.w;
            }
            st4[c*32+tx] = acc;
        }
        __syncthreads();
        for (int cc=0; cc<16; cc++){
            int c = wid*16+cc;
            float4 acc = make_float4(0.f,0.f,0.f,0.f);
            for (int r=0; r<64; r++){
                float a = sC[r*64+c];
                float4 v = st4[r*32 + tx];
                acc.x += a*v.x; acc.y += a*v.y; acc.z += a*v.z; acc.w += a*v.w;
            }
            xqout[(b*64+c)*32 + tx] = acc;
        }
    }
}

// ---------------- score softmax + top-k + outputs + A2 ----------------
__global__ void k_topkA2(const float* __restrict__ x, float* __restrict__ out){
    __shared__ float sA[NPG*NPG];
    __shared__ float sS[NPG*NPG];
    __shared__ float sU[NPG*KK];
    __shared__ float s[64];
    __shared__ float red[64];
    __shared__ int lp[KK];
    int b = blockIdx.x, t = threadIdx.x;
    if (t < 64){ float v = g_f[b*64+t] + g_f[NNODES + b*64+t]; s[t] = v; red[t] = v; }
    __syncthreads();
    for (int o=32; o>0; o>>=1){ if (t<o) red[t] = fmaxf(red[t], red[t+o]); __syncthreads(); }
    float m = red[0];
    __syncthreads();
    if (t < 64){ float e = expf(s[t] - m); s[t] = e; red[t] = e; }
    __syncthreads();
    for (int o=32; o>0; o>>=1){ if (t<o) red[t] += red[t+o]; __syncthreads(); }
    float den = red[0];
    __syncthreads();
    if (t < 64) s[t] = s[t] / den;
    __syncthreads();
    if (t < 64){
        float v = s[t];
        int rank = 0;
        for (int j=0; j<64; j++){
            float u = s[j];
            rank += (u > v) || (u == v && j < t);
        }
        if (rank < KK){
            lp[rank] = t;
            out[OFF_B + b*KK+rank] = (float)b;
            out[OFF_P + b*KK+rank] = (float)(b*64+t);
        }
    }
    __syncthreads();
    {
        const float4* x4 = (const float4*)x;
        float4* o4 = (float4*)out;
        for (int i=t; i<KK*32; i+=256){
            int r = i >> 5, f = i & 31;
            int p = lp[r];
            float sc = s[p];
            float4 v = x4[(b*64+p)*32 + f];
            o4[(size_t)(b*KK+r)*32 + f] = make_float4(v.x*sc, v.y*sc, v.z*sc, v.w*sc);
        }
    }
    {
        float4 z4 = make_float4(0.f,0.f,0.f,0.f);
        float4* a4 = (float4*)(out + OFF_A2);
        for (int idx=t; idx<KK*NK4; idx+=256){
            int i2 = idx / NK4, c4 = idx - i2*NK4;
            a4[(size_t)(b*KK+i2)*NK4 + c4] = z4;
        }
    }
    for (int i=t; i<NPG*NPG; i+=256){ sA[i] = g_A[b*NPG*NPG+i]; sS[i] = g_S[b*NPG*NPG+i]; }
    __syncthreads();
    for (int idx=t; idx<NPG*KK; idx+=256){
        int r = idx / KK, j = idx - r*KK;
        int pj = lp[j];
        float acc = 0.f;
        for (int c=0; c<NPG; c++) acc += sA[r*NPG+c]*sS[c*NPG+pj];
        sU[idx] = acc;
    }
    __syncthreads();
    for (int idx=t; idx<KK*KK; idx+=256){
        int i2 = idx / KK, j = idx - i2*KK;
        int pi = lp[i2];
        float acc = 0.f;
        for (int r=0; r<NPG; r++) acc += sS[r*NPG+pi]*sU[r*KK+j];
        float v = (i2 == j) ? 1.0f : acc;
        out[(size_t)OFF_A2 + (size_t)(b*KK+i2)*NK + (b*KK+j)] = v;
    }
}

// ---------------- host ----------------
static void launch_attention(int base,
                             const __nv_bfloat16* kvP,
                             const float* q0, const float* q1,
                             const float* W3,
                             __nv_bfloat16* wkP, __nv_bfloat16* w1P,
                             __nv_bfloat16* h0P, __nv_bfloat16* h1P)
{
    k_pgemm<3><<<dim3(1,64,2),128,GSMEM>>>(
        kvP, 0LL, (long long)NNODES*HD,
        wkP + (size_t)base*16384, 16384LL, 4LL*16384,
        128, 128,
        h0P, (long long)NNODES*H0W, 2LL*NNODES*H0W,
        q0, q1);
    k_pgemm<2><<<dim3(2,64,2),128,GSMEM>>>(
        h0P, (long long)NNODES*H0W, 2LL*NNODES*H0W,
        w1P + (size_t)base*256*H0W, 256LL*H0W, 4LL*256*H0W,
        H0W, 256,
        h1P, (long long)NNODES*256, 2LL*NNODES*256,
        nullptr, nullptr);
    k_w2s<<<dim3(1,64,2),128,GSMEM>>>(W3, base);
}

extern "C" void kernel_launch(void* const* d_in, const int* in_sizes, int n_in,
                              void* d_out, int out_size)
{
    (void)in_sizes; (void)n_in; (void)out_size;
    const float* x    = (const float*)d_in[0];
    const int*   ei   = (const int*)  d_in[1];
    const float* ew   = (const float*)d_in[2];
    const float* txg  = (const float*)d_in[3];
    const float* Wk   = (const float*)d_in[5];
    const float* W1   = (const float*)d_in[6];
    const float* W2   = (const float*)d_in[7];
    const float* W3   = (const float*)d_in[8];
    const float* linW = (const float*)d_in[9];
    float* out = (float*)d_out;
    const int* row = ei;
    const int* col = ei + NE;

    cudaFuncSetAttribute(k_pgemm<2>,   cudaFuncAttributeMaxDynamicSharedMemorySize, GSMEM);
    cudaFuncSetAttribute(k_pgemm<3>,   cudaFuncAttributeMaxDynamicSharedMemorySize, GSMEM);
    cudaFuncSetAttribute(k_w2s,        cudaFuncAttributeMaxDynamicSharedMemorySize, GSMEM);
    cudaFuncSetAttribute(k_prep_graph, cudaFuncAttributeMaxDynamicSharedMemorySize, 98304);
    cudaFuncSetAttribute(k_fuse,       cudaFuncAttributeMaxDynamicSharedMemorySize, FUSE_SMEM);

    float *p_xq,*p_qt;
    __nv_bfloat16 *p_XP,*p_xcP,*p_WkP,*p_W1P,*p_h0P,*p_h1P;
    cudaGetSymbolAddress((void**)&p_xq,   g_xq);
    cudaGetSymbolAddress((void**)&p_qt,   g_qt);
    cudaGetSymbolAddress((void**)&p_XP,   g_XP);
    cudaGetSymbolAddress((void**)&p_xcP,  g_xcP);
    cudaGetSymbolAddress((void**)&p_WkP,  g_WkP);
    cudaGetSymbolAddress((void**)&p_W1P,  g_W1P);
    cudaGetSymbolAddress((void**)&p_h0P,  g_h0P);
    cudaGetSymbolAddress((void**)&p_h1P,  g_h1P);

    // 1. prep + graph build + hop^2(x)
    k_prep_graph<<<NBATCH + PREP_BLOCKS, 256, 98304>>>(Wk, W1, W2, linW, x, txg,
                                                       row, col, ew, (float4*)p_xq);
    // 2-4. f1 = att(x, xq); f2 = att(x, qt)
    launch_attention(0, p_XP, p_xq, p_qt, W3, p_WkP, p_W1P, p_h0P, p_h1P);
    // 5. fused edge softmax + agg + linW GEMM + xc + split + hop^2
    k_fuse<<<NBATCH,128,FUSE_SMEM>>>(x, (float4*)p_xq);
    // 6-8. g1 = att(xc, xq2); g2 = att(xc, qt)
    launch_attention(2, p_xcP, p_xq, p_qt, W3, p_WkP, p_W1P, p_h0P, p_h1P);
    // 9. score softmax + top-k + outputs + A2
    k_topkA2<<<NBATCH,256>>>(x, out);
}